// round 16
// baseline (speedup 1.0000x reference)
#include <cuda_runtime.h>
#include <math.h>

#define NB   256
#define NC   768
#define NH   24
#define NHW  576
#define EMBD 2304
#define HM_Z  4          // z-chunks for heatmap (192 ch each)
#define PL_CHUNKS 6      // channel chunks for masked pooling (128 ch each)
#define KSPLIT 12
#define KB (EMBD / KSPLIT)   // 192
#define NG   16          // pipeline groups
#define GB   (NB / NG)   // 16 batches per group (32 units = 56.6MB)

// ---- packed f32x2 helpers -------------------------------------------------
__device__ __forceinline__ void fma2(unsigned long long& acc,
                                     unsigned long long a, unsigned long long b) {
    asm("fma.rn.f32x2 %0, %1, %2, %0;" : "+l"(acc) : "l"(a), "l"(b));
}
__device__ __forceinline__ void add2(unsigned long long& acc, unsigned long long a) {
    asm("add.rn.f32x2 %0, %1, %0;" : "+l"(acc) : "l"(a));
}
__device__ __forceinline__ float2 unpack2(unsigned long long v) {
    float2 r;
    asm("mov.b64 {%0, %1}, %2;" : "=f"(r.x), "=f"(r.y) : "l"(v));
    return r;
}

// Scratch (allocation-free rule: __device__ globals)
__device__ float g_hmp[2][NB][HM_Z][NHW];        // partial heatmaps (4.7MB)
__device__ float g_emb[2][NB][EMBD];
__device__ float g_lpart[KSPLIT][NB][NB];        // GEMM K-split partials (3MB)
__device__ float g_logits[NB][NB];
__device__ float g_logitsT[NB][NB];
__device__ float g_rowloss[NB];

// ---------------------------------------------------------------------------
// K1: partial heatmaps for one group. grid (GB, 2, HM_Z), block 576.
// ---------------------------------------------------------------------------
__global__ __launch_bounds__(NHW) void hm_kernel(const float* __restrict__ f1,
                                                 const float* __restrict__ f2,
                                                 int b0) {
    const int img = blockIdx.y;
    const int b   = b0 + blockIdx.x;
    const int z   = blockIdx.z;
    const int g   = threadIdx.x / 144;
    const int s   = threadIdx.x % 144;

    __shared__ __align__(16) float4 s_part[4][144];

    const float* fb = (img ? f2 : f1) + (size_t)b * NC * NHW
                    + (size_t)(z * 192 + g * 48) * NHW;
    const float4* __restrict__ base = (const float4*)fb + s;

    float ax = 0.f, ay = 0.f, az = 0.f, aw = 0.f;
    #pragma unroll 8
    for (int ci = 0; ci < 48; ci++) {
        float4 v = base[(size_t)ci * 144];       // 144 float4 per channel row
        ax += v.x; ay += v.y; az += v.z; aw += v.w;
    }
    s_part[g][s] = make_float4(ax, ay, az, aw);
    __syncthreads();

    if (g == 0) {                                 // 144 threads finalize
        float4 p0 = s_part[0][s], p1 = s_part[1][s];
        float4 p2 = s_part[2][s], p3 = s_part[3][s];
        float4 o = make_float4((p0.x + p1.x) + (p2.x + p3.x),
                               (p0.y + p1.y) + (p2.y + p3.y),
                               (p0.z + p1.z) + (p2.z + p3.z),
                               (p0.w + p1.w) + (p2.w + p3.w));
        ((float4*)&g_hmp[img][b][z][0])[s] = o;
    }
}

// ---------------------------------------------------------------------------
// K2: masked pooling for one group, masks computed inline from g_hmp.
// grid (GB, 2, PL_CHUNKS), 256 thr. Feature re-reads should hit L2 (pipelined
// on a forked stream right behind the group's hm_kernel).
// ---------------------------------------------------------------------------
__global__ __launch_bounds__(256) void pool_kernel(const float* __restrict__ f1,
                                                   const float* __restrict__ f2,
                                                   int b0) {
    const int img = blockIdx.y;
    const int b   = b0 + blockIdx.x;
    const int ch0 = blockIdx.z * (NC / PL_CHUNKS);
    const float* __restrict__ fb = (img ? f2 : f1) + (size_t)b * NC * NHW;
    const int t = threadIdx.x;

    __shared__ float s_hm[NHW];
    __shared__ __align__(16) float s_mmax[NHW];
    __shared__ __align__(16) float s_mmin[NHW];
    __shared__ int  s_cnt[16];
    __shared__ float s_inv[2];

    // heatmap from partials (L2-hot, 9KB)
    for (int i = t; i < NHW; i += 256) {
        s_hm[i] = g_hmp[img][b][0][i] + g_hmp[img][b][1][i]
                + g_hmp[img][b][2][i] + g_hmp[img][b][3][i];
    }
    __syncthreads();

    // masks: 3x3 border-clipped local max/min; corners never peaks
    int cmax = 0, cmin = 0;
    for (int i = t; i < NHW; i += 256) {
        const int h = i / NH, w = i % NH;
        const float v = s_hm[i];
        float mx = v, mn = v;
        #pragma unroll
        for (int dh = -1; dh <= 1; dh++) {
            #pragma unroll
            for (int dw = -1; dw <= 1; dw++) {
                int hh = h + dh, ww = w + dw;
                if (hh >= 0 && hh < NH && ww >= 0 && ww < NH) {
                    float nb = s_hm[hh * NH + ww];
                    mx = fmaxf(mx, nb);
                    mn = fminf(mn, nb);
                }
            }
        }
        const bool corner = (h == 0 || h == NH - 1) && (w == 0 || w == NH - 1);
        const bool ismax  = (v >= mx) && !corner;
        const bool ismin  = (v <= mn) && !corner;
        s_mmax[i] = ismax ? 1.f : 0.f;
        s_mmin[i] = ismin ? 1.f : 0.f;
        cmax += (int)ismax;
        cmin += (int)ismin;
    }
    const int warp = t >> 5;
    const int lane = t & 31;
    #pragma unroll
    for (int off = 16; off > 0; off >>= 1) {
        cmax += __shfl_down_sync(0xffffffffu, cmax, off);
        cmin += __shfl_down_sync(0xffffffffu, cmin, off);
    }
    if (lane == 0) { s_cnt[warp] = cmax; s_cnt[8 + warp] = cmin; }
    __syncthreads();
    if (t == 0) {
        int nmax = 0, nmin = 0;
        #pragma unroll
        for (int i = 0; i < 8; i++) { nmax += s_cnt[i]; nmin += s_cnt[8 + i]; }
        s_inv[0] = 1.f / (float)nmax;
        s_inv[1] = 1.f / (float)nmin;
    }
    __syncthreads();

    // masked pooling (packed f32x2), masks in smem
    const float invmax = s_inv[0];
    const float invmin = s_inv[1];
    const float invgap = 1.f / (float)NHW;
    const ulonglong2* __restrict__ m2a = (const ulonglong2*)s_mmax;
    const ulonglong2* __restrict__ m2i = (const ulonglong2*)s_mmin;
    float* __restrict__ eb = &g_emb[img][b][0];

    #pragma unroll 2
    for (int ci = 0; ci < 16; ci++) {
        const int c = ch0 + warp + (ci << 3);
        const ulonglong2* __restrict__ row2 = (const ulonglong2*)(fb + (size_t)c * NHW);

        unsigned long long am = 0ull, ai = 0ull, ag = 0ull;
        #pragma unroll
        for (int i = 0; i < 4; i++) {                // 4*32 = 128 of 144 float4
            int idx = lane + (i << 5);
            ulonglong2 x  = row2[idx];
            ulonglong2 ma = m2a[idx];
            ulonglong2 mi = m2i[idx];
            fma2(am, x.x, ma.x); fma2(am, x.y, ma.y);
            fma2(ai, x.x, mi.x); fma2(ai, x.y, mi.y);
            add2(ag, x.x);       add2(ag, x.y);
        }
        if (lane < 16) {                             // remaining 16 float4
            int idx = 128 + lane;
            ulonglong2 x  = row2[idx];
            ulonglong2 ma = m2a[idx];
            ulonglong2 mi = m2i[idx];
            fma2(am, x.x, ma.x); fma2(am, x.y, ma.y);
            fma2(ai, x.x, mi.x); fma2(ai, x.y, mi.y);
            add2(ag, x.x);       add2(ag, x.y);
        }
        float2 fm = unpack2(am), fi = unpack2(ai), fg = unpack2(ag);
        float smax = fm.x + fm.y, smin = fi.x + fi.y, sgap = fg.x + fg.y;
        #pragma unroll
        for (int off = 16; off > 0; off >>= 1) {
            smax += __shfl_down_sync(0xffffffffu, smax, off);
            smin += __shfl_down_sync(0xffffffffu, smin, off);
            sgap += __shfl_down_sync(0xffffffffu, sgap, off);
        }
        if (lane == 0) {
            eb[c]          = smax * invmax;
            eb[NC + c]     = smin * invmin;
            eb[2 * NC + c] = sgap * invgap;
        }
    }
}

// ---------------------------------------------------------------------------
// L2-normalize each 2304-d embedding in place. One block per (img, b).
// ---------------------------------------------------------------------------
__global__ __launch_bounds__(256) void norm_kernel() {
    const int img = blockIdx.y, b = blockIdx.x;
    float* __restrict__ e = &g_emb[img][b][0];

    float vals[9];
    float ss = 0.f;
    #pragma unroll
    for (int q = 0; q < 9; q++) {
        float x = e[threadIdx.x + q * 256];
        vals[q] = x;
        ss += x * x;
    }
    #pragma unroll
    for (int off = 16; off > 0; off >>= 1)
        ss += __shfl_xor_sync(0xffffffffu, ss, off);

    __shared__ float sred[8];
    __shared__ float s_inv;
    if ((threadIdx.x & 31) == 0) sred[threadIdx.x >> 5] = ss;
    __syncthreads();
    if (threadIdx.x == 0) {
        float t = 0.f;
        #pragma unroll
        for (int i = 0; i < 8; i++) t += sred[i];
        s_inv = 1.f / sqrtf(t);
    }
    __syncthreads();
    const float inv = s_inv;
    #pragma unroll
    for (int q = 0; q < 9; q++) e[threadIdx.x + q * 256] = vals[q] * inv;
}

// ---------------------------------------------------------------------------
// GEMM: 64x64 tile, 16x16 threads, 4x4 per thread, K-split 12 (192 CTAs).
// ---------------------------------------------------------------------------
__global__ __launch_bounds__(256) void gemm_kernel() {
    __shared__ __align__(16) float As[32][68];   // [k][m], pad 4 keeps 16B align
    __shared__ __align__(16) float Bs[32][68];
    const int tx = threadIdx.x, ty = threadIdx.y;       // 16x16
    const int tid = ty * 16 + tx;
    const int bi = blockIdx.y * 64, bj = blockIdx.x * 64;
    const int kb0 = blockIdx.z * KB;

    const int lm = tid >> 2;          // 0..63 : m row to load
    const int lk = (tid & 3) * 8;     // 0,8,16,24 : k start (8 floats)

    float acc[4][4];
    #pragma unroll
    for (int i = 0; i < 4; i++)
        #pragma unroll
        for (int j = 0; j < 4; j++) acc[i][j] = 0.f;

    for (int kc = 0; kc < KB; kc += 32) {
        const int kg = kb0 + kc + lk;
        float4 a0 = *(const float4*)&g_emb[0][bi + lm][kg];
        float4 a1 = *(const float4*)&g_emb[0][bi + lm][kg + 4];
        float4 b0 = *(const float4*)&g_emb[1][bj + lm][kg];
        float4 b1 = *(const float4*)&g_emb[1][bj + lm][kg + 4];
        As[lk + 0][lm] = a0.x; As[lk + 1][lm] = a0.y; As[lk + 2][lm] = a0.z; As[lk + 3][lm] = a0.w;
        As[lk + 4][lm] = a1.x; As[lk + 5][lm] = a1.y; As[lk + 6][lm] = a1.z; As[lk + 7][lm] = a1.w;
        Bs[lk + 0][lm] = b0.x; Bs[lk + 1][lm] = b0.y; Bs[lk + 2][lm] = b0.z; Bs[lk + 3][lm] = b0.w;
        Bs[lk + 4][lm] = b1.x; Bs[lk + 5][lm] = b1.y; Bs[lk + 6][lm] = b1.z; Bs[lk + 7][lm] = b1.w;
        __syncthreads();

        #pragma unroll
        for (int k = 0; k < 32; k++) {
            float4 av = *(const float4*)&As[k][ty * 4];
            float4 bv = *(const float4*)&Bs[k][tx * 4];
            float a[4] = {av.x, av.y, av.z, av.w};
            float bb[4] = {bv.x, bv.y, bv.z, bv.w};
            #pragma unroll
            for (int i = 0; i < 4; i++)
                #pragma unroll
                for (int j = 0; j < 4; j++)
                    acc[i][j] = fmaf(a[i], bb[j], acc[i][j]);
        }
        __syncthreads();
    }

    #pragma unroll
    for (int i = 0; i < 4; i++) {
        float4 v = make_float4(acc[i][0], acc[i][1], acc[i][2], acc[i][3]);
        *(float4*)&g_lpart[blockIdx.z][bi + ty * 4 + i][bj + tx * 4] = v;
    }
}

// ---------------------------------------------------------------------------
// Reduce K-split partials, apply scale, emit logits and logitsT.
// ---------------------------------------------------------------------------
__global__ __launch_bounds__(256) void reduce_kernel(const float* __restrict__ scale_p) {
    const int r = blockIdx.x, t = threadIdx.x;
    float v = 0.f;
    #pragma unroll
    for (int z = 0; z < KSPLIT; z++) v += g_lpart[z][r][t];
    v *= __ldg(scale_p);
    g_logits[r][t]  = v;
    g_logitsT[t][r] = v;
}

// ---------------------------------------------------------------------------
// Per-row: lse(row of logits) + lse(row of logitsT) - 2*diag
// ---------------------------------------------------------------------------
__global__ __launch_bounds__(256) void lse_kernel() {
    const int r = blockIdx.x, t = threadIdx.x;
    const int warp = t >> 5, lane = t & 31;
    __shared__ float sred[8];

    const float x1 = g_logits[r][t];
    const float x2 = g_logitsT[r][t];

    float m = x1;
    #pragma unroll
    for (int off = 16; off > 0; off >>= 1) m = fmaxf(m, __shfl_xor_sync(0xffffffffu, m, off));
    if (lane == 0) sred[warp] = m;
    __syncthreads();
    float m1 = sred[0];
    #pragma unroll
    for (int i = 1; i < 8; i++) m1 = fmaxf(m1, sred[i]);
    __syncthreads();

    float e1 = expf(x1 - m1);
    #pragma unroll
    for (int off = 16; off > 0; off >>= 1) e1 += __shfl_xor_sync(0xffffffffu, e1, off);
    if (lane == 0) sred[warp] = e1;
    __syncthreads();
    float s1 = 0.f;
    #pragma unroll
    for (int i = 0; i < 8; i++) s1 += sred[i];
    __syncthreads();

    float n = x2;
    #pragma unroll
    for (int off = 16; off > 0; off >>= 1) n = fmaxf(n, __shfl_xor_sync(0xffffffffu, n, off));
    if (lane == 0) sred[warp] = n;
    __syncthreads();
    float m2 = sred[0];
    #pragma unroll
    for (int i = 1; i < 8; i++) m2 = fmaxf(m2, sred[i]);
    __syncthreads();

    float e2 = expf(x2 - m2);
    #pragma unroll
    for (int off = 16; off > 0; off >>= 1) e2 += __shfl_xor_sync(0xffffffffu, e2, off);
    if (lane == 0) sred[warp] = e2;
    __syncthreads();
    float s2 = 0.f;
    #pragma unroll
    for (int i = 0; i < 8; i++) s2 += sred[i];

    if (t == 0) {
        float lse1 = m1 + logf(s1);
        float lse2 = m2 + logf(s2);
        g_rowloss[r] = lse1 + lse2 - 2.f * g_logits[r][r];
    }
}

// ---------------------------------------------------------------------------
// Final scalar: mean over rows, /2 (symmetric CE), write to d_out.
// ---------------------------------------------------------------------------
__global__ __launch_bounds__(256) void final_kernel(float* __restrict__ out) {
    float v = g_rowloss[threadIdx.x];
    #pragma unroll
    for (int off = 16; off > 0; off >>= 1)
        v += __shfl_xor_sync(0xffffffffu, v, off);
    __shared__ float sred[8];
    if ((threadIdx.x & 31) == 0) sred[threadIdx.x >> 5] = v;
    __syncthreads();
    if (threadIdx.x == 0) {
        float t = 0.f;
        #pragma unroll
        for (int i = 0; i < 8; i++) t += sred[i];
        out[0] = t * (1.0f / 512.0f);
    }
}

extern "C" void kernel_launch(void* const* d_in, const int* in_sizes, int n_in,
                              void* d_out, int out_size) {
    (void)in_sizes; (void)n_in; (void)out_size;
    const float* f1    = (const float*)d_in[0];
    const float* f2    = (const float*)d_in[1];
    const float* scale = (const float*)d_in[2];

    // Lazily create the aux stream + events OUTSIDE of graph capture only
    // (object creation is capture-unsafe). The harness always runs a
    // correctness call before capture, so these exist by capture time.
    // During capture we only use record/wait, which are capture-legal and
    // produce the fork/join graph structure. No device memory involved.
    static cudaStream_t aux = nullptr;
    static cudaEvent_t  ev[NG];
    static cudaEvent_t  evj = nullptr;
    cudaStreamCaptureStatus cap = cudaStreamCaptureStatusNone;
    cudaStreamIsCapturing((cudaStream_t)0, &cap);
    if (cap == cudaStreamCaptureStatusNone && aux == nullptr) {
        cudaStreamCreateWithFlags(&aux, cudaStreamNonBlocking);
        for (int g = 0; g < NG; g++)
            cudaEventCreateWithFlags(&ev[g], cudaEventDisableTiming);
        cudaEventCreateWithFlags(&evj, cudaEventDisableTiming);
    }

    // Fork/join pipeline: hm(g) on the launch stream; pool(g) on aux gated
    // by an event, overlapping hm(g+1) and re-reading group g from L2.
    for (int g = 0; g < NG; g++) {
        hm_kernel<<<dim3(GB, 2, HM_Z), NHW>>>(f1, f2, g * GB);
        cudaEventRecord(ev[g], 0);
        cudaStreamWaitEvent(aux, ev[g], 0);
        pool_kernel<<<dim3(GB, 2, PL_CHUNKS), 256, 0, aux>>>(f1, f2, g * GB);
    }
    cudaEventRecord(evj, aux);
    cudaStreamWaitEvent(0, evj, 0);

    norm_kernel  <<<dim3(NB, 2), 256>>>();
    gemm_kernel  <<<dim3(4, 4, KSPLIT), dim3(16, 16)>>>();
    reduce_kernel<<<NB, 256>>>(scale);
    lse_kernel   <<<NB, 256>>>();
    final_kernel <<<1, 256>>>((float*)d_out);
}

// round 17
// speedup vs baseline: 1.2183x; 1.2183x over previous
#include <cuda_runtime.h>
#include <math.h>

#define NB   256
#define NC   768
#define NH   24
#define NHW  576
#define EMBD 2304
#define HM_Z  4          // z-chunks for heatmap (192 ch each)
#define PL_CHUNKS 6      // channel chunks for masked pooling (128 ch each)
#define KSPLIT 12
#define KB (EMBD / KSPLIT)   // 192

// ---- packed f32x2 helpers -------------------------------------------------
__device__ __forceinline__ void fma2(unsigned long long& acc,
                                     unsigned long long a, unsigned long long b) {
    asm("fma.rn.f32x2 %0, %1, %2, %0;" : "+l"(acc) : "l"(a), "l"(b));
}
__device__ __forceinline__ void add2(unsigned long long& acc, unsigned long long a) {
    asm("add.rn.f32x2 %0, %1, %0;" : "+l"(acc) : "l"(a));
}
__device__ __forceinline__ float2 unpack2(unsigned long long v) {
    float2 r;
    asm("mov.b64 {%0, %1}, %2;" : "=f"(r.x), "=f"(r.y) : "l"(v));
    return r;
}

// Scratch (allocation-free rule: __device__ globals)
__device__ float g_hmp[2][NB][HM_Z][NHW];        // partial heatmaps (4.7MB)
__device__ float g_mask[2][NB][2][NHW];          // [0]=max mask, [1]=min mask
__device__ float g_inv[2][NB][2];                // 1/nmax, 1/nmin
__device__ float g_emb[2][NB][EMBD];
__device__ float g_lpart[KSPLIT][NB][NB];        // GEMM K-split partials (3MB)
__device__ float g_logits[NB][NB];
__device__ float g_logitsT[NB][NB];
__device__ float g_rowloss[NB];

// ---------------------------------------------------------------------------
// K1: partial heatmaps. grid (NB, 2, HM_Z), block 576.
// Thread = (group g = t/144, slot s = t%144); owns 4 pixels (float4 slot s),
// sums 48 channels. Groups block-reduced in smem -> ONE partial per block.
// ---------------------------------------------------------------------------
__global__ __launch_bounds__(NHW) void hm_kernel(const float* __restrict__ f1,
                                                 const float* __restrict__ f2) {
    const int img = blockIdx.y;
    const int b   = blockIdx.x;
    const int z   = blockIdx.z;
    const int g   = threadIdx.x / 144;
    const int s   = threadIdx.x % 144;

    __shared__ __align__(16) float4 s_part[4][144];

    const float* fb = (img ? f2 : f1) + (size_t)b * NC * NHW
                    + (size_t)(z * 192 + g * 48) * NHW;
    const float4* __restrict__ base = (const float4*)fb + s;

    float ax = 0.f, ay = 0.f, az = 0.f, aw = 0.f;
    #pragma unroll 8
    for (int ci = 0; ci < 48; ci++) {
        float4 v = base[(size_t)ci * 144];       // 144 float4 per channel row
        ax += v.x; ay += v.y; az += v.z; aw += v.w;
    }
    s_part[g][s] = make_float4(ax, ay, az, aw);
    __syncthreads();

    if (g == 0) {                                 // 144 threads finalize
        float4 p0 = s_part[0][s], p1 = s_part[1][s];
        float4 p2 = s_part[2][s], p3 = s_part[3][s];
        float4 o = make_float4((p0.x + p1.x) + (p2.x + p3.x),
                               (p0.y + p1.y) + (p2.y + p3.y),
                               (p0.z + p1.z) + (p2.z + p3.z),
                               (p0.w + p1.w) + (p2.w + p3.w));
        ((float4*)&g_hmp[img][b][z][0])[s] = o;
    }
}

// ---------------------------------------------------------------------------
// K2: masks from heatmap. grid (NB, 2), block 576. Tiny.
// ---------------------------------------------------------------------------
__global__ __launch_bounds__(NHW) void mask_kernel() {
    const int img = blockIdx.y, b = blockIdx.x, hw = threadIdx.x;
    __shared__ float s_hm[NHW];

    float v = 0.f;
    #pragma unroll
    for (int p = 0; p < HM_Z; p++) v += g_hmp[img][b][p][hw];
    s_hm[hw] = v;
    __syncthreads();

    const int h = hw / NH, w = hw % NH;
    float mx = v, mn = v;
    #pragma unroll
    for (int dh = -1; dh <= 1; dh++) {
        #pragma unroll
        for (int dw = -1; dw <= 1; dw++) {
            int hh = h + dh, ww = w + dw;
            if (hh >= 0 && hh < NH && ww >= 0 && ww < NH) {
                float nb = s_hm[hh * NH + ww];
                mx = fmaxf(mx, nb);
                mn = fminf(mn, nb);
            }
        }
    }
    const bool corner = (h == 0 || h == NH - 1) && (w == 0 || w == NH - 1);
    const bool ismax  = (v >= mx) && !corner;
    const bool ismin  = (v <= mn) && !corner;
    g_mask[img][b][0][hw] = ismax ? 1.f : 0.f;
    g_mask[img][b][1][hw] = ismin ? 1.f : 0.f;
    const int nmax = __syncthreads_count(ismax);
    const int nmin = __syncthreads_count(ismin);
    if (hw == 0) {
        g_inv[img][b][0] = 1.f / (float)nmax;
        g_inv[img][b][1] = 1.f / (float)nmin;
    }
}

// ---------------------------------------------------------------------------
// K3: masked pooling with packed f32x2 FMAs. grid (NB, 2, PL_CHUNKS), 256 thr.
// ---------------------------------------------------------------------------
__global__ __launch_bounds__(256) void pool_kernel(const float* __restrict__ f1,
                                                   const float* __restrict__ f2) {
    const int img = blockIdx.y;
    const int b   = blockIdx.x;
    const int ch0 = blockIdx.z * (NC / PL_CHUNKS);
    const float* __restrict__ fb = (img ? f2 : f1) + (size_t)b * NC * NHW;

    __shared__ __align__(16) float s_mmax[NHW];
    __shared__ __align__(16) float s_mmin[NHW];
    __shared__ float s_inv[2];

    for (int i = threadIdx.x; i < NHW; i += 256) {
        s_mmax[i] = g_mask[img][b][0][i];
        s_mmin[i] = g_mask[img][b][1][i];
    }
    if (threadIdx.x < 2) s_inv[threadIdx.x] = g_inv[img][b][threadIdx.x];
    __syncthreads();

    const int warp = threadIdx.x >> 5;
    const int lane = threadIdx.x & 31;
    const float invmax = s_inv[0];
    const float invmin = s_inv[1];
    const float invgap = 1.f / (float)NHW;
    const ulonglong2* __restrict__ m2a = (const ulonglong2*)s_mmax;
    const ulonglong2* __restrict__ m2i = (const ulonglong2*)s_mmin;
    float* __restrict__ eb = &g_emb[img][b][0];

    #pragma unroll 2
    for (int ci = 0; ci < 16; ci++) {
        const int c = ch0 + warp + (ci << 3);
        const ulonglong2* __restrict__ row2 = (const ulonglong2*)(fb + (size_t)c * NHW);

        unsigned long long am = 0ull, ai = 0ull, ag = 0ull;
        #pragma unroll
        for (int i = 0; i < 4; i++) {                // 4*32 = 128 of 144 float4
            int idx = lane + (i << 5);
            ulonglong2 x  = row2[idx];
            ulonglong2 ma = m2a[idx];
            ulonglong2 mi = m2i[idx];
            fma2(am, x.x, ma.x); fma2(am, x.y, ma.y);
            fma2(ai, x.x, mi.x); fma2(ai, x.y, mi.y);
            add2(ag, x.x);       add2(ag, x.y);
        }
        if (lane < 16) {                             // remaining 16 float4
            int idx = 128 + lane;
            ulonglong2 x  = row2[idx];
            ulonglong2 ma = m2a[idx];
            ulonglong2 mi = m2i[idx];
            fma2(am, x.x, ma.x); fma2(am, x.y, ma.y);
            fma2(ai, x.x, mi.x); fma2(ai, x.y, mi.y);
            add2(ag, x.x);       add2(ag, x.y);
        }
        float2 fm = unpack2(am), fi = unpack2(ai), fg = unpack2(ag);
        float smax = fm.x + fm.y, smin = fi.x + fi.y, sgap = fg.x + fg.y;
        #pragma unroll
        for (int off = 16; off > 0; off >>= 1) {
            smax += __shfl_down_sync(0xffffffffu, smax, off);
            smin += __shfl_down_sync(0xffffffffu, smin, off);
            sgap += __shfl_down_sync(0xffffffffu, sgap, off);
        }
        if (lane == 0) {
            eb[c]          = smax * invmax;
            eb[NC + c]     = smin * invmin;
            eb[2 * NC + c] = sgap * invgap;
        }
    }
}

// ---------------------------------------------------------------------------
// L2-normalize each 2304-d embedding in place. One block per (img, b).
// ---------------------------------------------------------------------------
__global__ __launch_bounds__(256) void norm_kernel() {
    const int img = blockIdx.y, b = blockIdx.x;
    float* __restrict__ e = &g_emb[img][b][0];

    float vals[9];
    float ss = 0.f;
    #pragma unroll
    for (int q = 0; q < 9; q++) {
        float x = e[threadIdx.x + q * 256];
        vals[q] = x;
        ss += x * x;
    }
    #pragma unroll
    for (int off = 16; off > 0; off >>= 1)
        ss += __shfl_xor_sync(0xffffffffu, ss, off);

    __shared__ float sred[8];
    __shared__ float s_inv;
    if ((threadIdx.x & 31) == 0) sred[threadIdx.x >> 5] = ss;
    __syncthreads();
    if (threadIdx.x == 0) {
        float t = 0.f;
        #pragma unroll
        for (int i = 0; i < 8; i++) t += sred[i];
        s_inv = 1.f / sqrtf(t);
    }
    __syncthreads();
    const float inv = s_inv;
    #pragma unroll
    for (int q = 0; q < 9; q++) e[threadIdx.x + q * 256] = vals[q] * inv;
}

// ---------------------------------------------------------------------------
// GEMM: 64x64 tile, 16x16 threads, 4x4 per thread, K-split 12 (192 CTAs).
// Transposed smem tiles ([k][m]) so inner loop does 2x LDS.128 per 16 FMA.
// ---------------------------------------------------------------------------
__global__ __launch_bounds__(256) void gemm_kernel() {
    __shared__ __align__(16) float As[32][68];   // [k][m], pad 4 keeps 16B align
    __shared__ __align__(16) float Bs[32][68];
    const int tx = threadIdx.x, ty = threadIdx.y;       // 16x16
    const int tid = ty * 16 + tx;
    const int bi = blockIdx.y * 64, bj = blockIdx.x * 64;
    const int kb0 = blockIdx.z * KB;

    const int lm = tid >> 2;          // 0..63 : m row to load
    const int lk = (tid & 3) * 8;     // 0,8,16,24 : k start (8 floats)

    float acc[4][4];
    #pragma unroll
    for (int i = 0; i < 4; i++)
        #pragma unroll
        for (int j = 0; j < 4; j++) acc[i][j] = 0.f;

    for (int kc = 0; kc < KB; kc += 32) {
        const int kg = kb0 + kc + lk;
        float4 a0 = *(const float4*)&g_emb[0][bi + lm][kg];
        float4 a1 = *(const float4*)&g_emb[0][bi + lm][kg + 4];
        float4 b0 = *(const float4*)&g_emb[1][bj + lm][kg];
        float4 b1 = *(const float4*)&g_emb[1][bj + lm][kg + 4];
        As[lk + 0][lm] = a0.x; As[lk + 1][lm] = a0.y; As[lk + 2][lm] = a0.z; As[lk + 3][lm] = a0.w;
        As[lk + 4][lm] = a1.x; As[lk + 5][lm] = a1.y; As[lk + 6][lm] = a1.z; As[lk + 7][lm] = a1.w;
        Bs[lk + 0][lm] = b0.x; Bs[lk + 1][lm] = b0.y; Bs[lk + 2][lm] = b0.z; Bs[lk + 3][lm] = b0.w;
        Bs[lk + 4][lm] = b1.x; Bs[lk + 5][lm] = b1.y; Bs[lk + 6][lm] = b1.z; Bs[lk + 7][lm] = b1.w;
        __syncthreads();

        #pragma unroll
        for (int k = 0; k < 32; k++) {
            float4 av = *(const float4*)&As[k][ty * 4];
            float4 bv = *(const float4*)&Bs[k][tx * 4];
            float a[4] = {av.x, av.y, av.z, av.w};
            float bb[4] = {bv.x, bv.y, bv.z, bv.w};
            #pragma unroll
            for (int i = 0; i < 4; i++)
                #pragma unroll
                for (int j = 0; j < 4; j++)
                    acc[i][j] = fmaf(a[i], bb[j], acc[i][j]);
        }
        __syncthreads();
    }

    #pragma unroll
    for (int i = 0; i < 4; i++) {
        float4 v = make_float4(acc[i][0], acc[i][1], acc[i][2], acc[i][3]);
        *(float4*)&g_lpart[blockIdx.z][bi + ty * 4 + i][bj + tx * 4] = v;
    }
}

// ---------------------------------------------------------------------------
// Reduce K-split partials, apply scale, emit logits and logitsT.
// grid (NB), block 256: thread t handles column t of row blockIdx.x.
// ---------------------------------------------------------------------------
__global__ __launch_bounds__(256) void reduce_kernel(const float* __restrict__ scale_p) {
    const int r = blockIdx.x, t = threadIdx.x;
    float v = 0.f;
    #pragma unroll
    for (int z = 0; z < KSPLIT; z++) v += g_lpart[z][r][t];
    v *= __ldg(scale_p);
    g_logits[r][t]  = v;
    g_logitsT[t][r] = v;
}

// ---------------------------------------------------------------------------
// Per-row: lse(row of logits) + lse(row of logitsT) - 2*diag
// ---------------------------------------------------------------------------
__global__ __launch_bounds__(256) void lse_kernel() {
    const int r = blockIdx.x, t = threadIdx.x;
    const int warp = t >> 5, lane = t & 31;
    __shared__ float sred[8];

    const float x1 = g_logits[r][t];
    const float x2 = g_logitsT[r][t];

    float m = x1;
    #pragma unroll
    for (int off = 16; off > 0; off >>= 1) m = fmaxf(m, __shfl_xor_sync(0xffffffffu, m, off));
    if (lane == 0) sred[warp] = m;
    __syncthreads();
    float m1 = sred[0];
    #pragma unroll
    for (int i = 1; i < 8; i++) m1 = fmaxf(m1, sred[i]);
    __syncthreads();

    float e1 = expf(x1 - m1);
    #pragma unroll
    for (int off = 16; off > 0; off >>= 1) e1 += __shfl_xor_sync(0xffffffffu, e1, off);
    if (lane == 0) sred[warp] = e1;
    __syncthreads();
    float s1 = 0.f;
    #pragma unroll
    for (int i = 0; i < 8; i++) s1 += sred[i];
    __syncthreads();

    float n = x2;
    #pragma unroll
    for (int off = 16; off > 0; off >>= 1) n = fmaxf(n, __shfl_xor_sync(0xffffffffu, n, off));
    if (lane == 0) sred[warp] = n;
    __syncthreads();
    float m2 = sred[0];
    #pragma unroll
    for (int i = 1; i < 8; i++) m2 = fmaxf(m2, sred[i]);
    __syncthreads();

    float e2 = expf(x2 - m2);
    #pragma unroll
    for (int off = 16; off > 0; off >>= 1) e2 += __shfl_xor_sync(0xffffffffu, e2, off);
    if (lane == 0) sred[warp] = e2;
    __syncthreads();
    float s2 = 0.f;
    #pragma unroll
    for (int i = 0; i < 8; i++) s2 += sred[i];

    if (t == 0) {
        float lse1 = m1 + logf(s1);
        float lse2 = m2 + logf(s2);
        g_rowloss[r] = lse1 + lse2 - 2.f * g_logits[r][r];
    }
}

// ---------------------------------------------------------------------------
// Final scalar: mean over rows, /2 (symmetric CE), write to d_out.
// ---------------------------------------------------------------------------
__global__ __launch_bounds__(256) void final_kernel(float* __restrict__ out) {
    float v = g_rowloss[threadIdx.x];
    #pragma unroll
    for (int off = 16; off > 0; off >>= 1)
        v += __shfl_xor_sync(0xffffffffu, v, off);
    __shared__ float sred[8];
    if ((threadIdx.x & 31) == 0) sred[threadIdx.x >> 5] = v;
    __syncthreads();
    if (threadIdx.x == 0) {
        float t = 0.f;
        #pragma unroll
        for (int i = 0; i < 8; i++) t += sred[i];
        out[0] = t * (1.0f / 512.0f);
    }
}

extern "C" void kernel_launch(void* const* d_in, const int* in_sizes, int n_in,
                              void* d_out, int out_size) {
    (void)in_sizes; (void)n_in; (void)out_size;
    const float* f1    = (const float*)d_in[0];
    const float* f2    = (const float*)d_in[1];
    const float* scale = (const float*)d_in[2];

    hm_kernel    <<<dim3(NB, 2, HM_Z),      NHW>>>(f1, f2);
    mask_kernel  <<<dim3(NB, 2),            NHW>>>();
    pool_kernel  <<<dim3(NB, 2, PL_CHUNKS), 256>>>(f1, f2);
    norm_kernel  <<<dim3(NB, 2),            256>>>();
    gemm_kernel  <<<dim3(4, 4, KSPLIT), dim3(16, 16)>>>();
    reduce_kernel<<<NB, 256>>>(scale);
    lse_kernel   <<<NB, 256>>>();
    final_kernel <<<1, 256>>>((float*)d_out);
}